// round 2
// baseline (speedup 1.0000x reference)
#include <cuda_runtime.h>
#include <cstdint>
#include <cstddef>

#define B_ 32
#define C_ 64
#define T_ 16384
#define K_ 21
#define TC_ 16364       // T - (K-1)
#define TP_ 16384       // padded time stride for scratch
#define TILE_T 128
#define NTILES 128      // ceil(TC_/TILE_T)
#define NEG 0.01f
#define WSLICE 1344     // C_ * K_ per branch per ci
#define SMEM_BYTES (64*148*4 + 2*2*WSLICE*8)   // xs + double-buffered packed w

// ---------------- device scratch (static: no allocations allowed) -----------
__device__ float  g_y[(size_t)2 * B_ * C_ * TP_];   // conv outputs, [br][b][co][t]
__device__ float2 g_wp[2 * C_ * C_ * K_];           // packed (w,w), [br][ci][co][k]
__device__ float  g_sum[2 * C_], g_sumsq[2 * C_];
__device__ float  g_scale[2 * C_], g_shift[2 * C_];
__device__ float  g_feat[B_ * 384];

// ---------------- f32x2 helpers (packed fp32 pair on the fma pipe) ----------
__device__ __forceinline__ unsigned long long pk(float lo, float hi) {
    unsigned long long r;
    asm("mov.b64 %0, {%1, %2};" : "=l"(r) : "f"(lo), "f"(hi));
    return r;
}
__device__ __forceinline__ void fma2(unsigned long long& a, unsigned long long x,
                                     unsigned long long w) {
    asm("fma.rn.f32x2 %0, %1, %2, %0;" : "+l"(a) : "l"(x), "l"(w));
}
__device__ __forceinline__ float2 upk(unsigned long long v) {
    float2 f;
    asm("mov.b64 {%0, %1}, %2;" : "=f"(f.x), "=f"(f.y) : "l"(v));
    return f;
}

// ---------------- kernel 0: zero per-channel stats --------------------------
__global__ void zero_kernel() {
    int i = threadIdx.x;
    if (i < 2 * C_) { g_sum[i] = 0.f; g_sumsq[i] = 0.f; }
}

// ---------------- kernel 1: pre-pack weights as (w,w) float2 ----------------
__global__ void wpack_kernel(const float* __restrict__ w1,
                             const float* __restrict__ w2) {
    int idx = blockIdx.x * blockDim.x + threadIdx.x;
    if (idx >= 2 * C_ * C_ * K_) return;
    int br = idx / (C_ * C_ * K_);
    int r  = idx - br * (C_ * C_ * K_);
    int ci = r / (C_ * K_);
    int r2 = r - ci * (C_ * K_);
    int co = r2 / K_;
    int k  = r2 - co * K_;
    const float* w = br ? w2 : w1;
    float v = w[(co * C_ + ci) * K_ + k];
    g_wp[idx] = make_float2(v, v);    // dst layout [br][ci][co][k] == idx
}

// ---------------- kernel 2: fused conv (both branches) + stats --------------
// block = 256 threads: tg = tid&15 (8 t-outputs each), cg = tid>>4 (4 co each)
// per thread: acc[2 br][4 co][4 f32x2 pairs] covering 8 consecutive t
__global__ __launch_bounds__(256, 1) void conv_kernel(const float* __restrict__ x) {
    extern __shared__ float sh[];
    float*  xs = sh;                                  // [64][148]
    float2* ws = (float2*)(sh + 64 * 148);            // [2 buf][2*WSLICE]

    const int b    = blockIdx.y;
    const int t0   = blockIdx.x * TILE_T;
    const int tid  = threadIdx.x;

    // stage x tile (all 64 input channels, TILE_T + K - 1 samples, zero-pad tail)
    for (int idx = tid; idx < 64 * 148; idx += 256) {
        int ci = idx / 148, tt = idx - ci * 148;
        int gt = t0 + tt;
        xs[idx] = (gt < T_) ? x[((size_t)b * C_ + ci) * T_ + gt] : 0.f;
    }
    // preload weight slice for ci = 0 into buffer 0
    for (int idx = tid; idx < 2 * WSLICE; idx += 256) {
        int br = idx / WSLICE;
        int r  = idx - br * WSLICE;
        ws[idx] = g_wp[(size_t)(br * C_ + 0) * WSLICE + r];
    }
    __syncthreads();

    const int tg = tid & 15;
    const int cg = tid >> 4;

    unsigned long long acc[2][4][4];
#pragma unroll
    for (int br = 0; br < 2; br++)
#pragma unroll
        for (int c = 0; c < 4; c++)
#pragma unroll
            for (int p = 0; p < 4; p++) acc[br][c][p] = 0ULL;

    for (int ci = 0; ci < C_; ++ci) {
        const int buf = ci & 1;
        // prefetch next ci's weight slice into the other buffer
        if (ci + 1 < C_) {
            for (int idx = tid; idx < 2 * WSLICE; idx += 256) {
                int br = idx / WSLICE;
                int r  = idx - br * WSLICE;
                ws[(buf ^ 1) * (2 * WSLICE) + idx] =
                    g_wp[(size_t)(br * C_ + (ci + 1)) * WSLICE + r];
            }
        }
        // pack this thread's x window (28 floats) into aligned/offset f32x2 pairs
        unsigned long long xe[14], xo[13];
        {
            const float4* xr = (const float4*)(xs + ci * 148 + tg * 8);
            float4 prev = xr[0];
            xe[0] = pk(prev.x, prev.y);
            xe[1] = pk(prev.z, prev.w);
            xo[0] = pk(prev.y, prev.z);
#pragma unroll
            for (int m = 1; m < 7; m++) {
                float4 q = xr[m];
                xo[2 * m - 1] = pk(prev.w, q.x);
                xe[2 * m]     = pk(q.x, q.y);
                xe[2 * m + 1] = pk(q.z, q.w);
                xo[2 * m]     = pk(q.y, q.z);
                prev = q;
            }
        }
        const float2* wrow = ws + buf * (2 * WSLICE);
#pragma unroll
        for (int k = 0; k < K_; k++) {
            unsigned long long wv[2][4];
#pragma unroll
            for (int br = 0; br < 2; br++)
#pragma unroll
                for (int c = 0; c < 4; c++)
                    wv[br][c] = *(const unsigned long long*)
                        &wrow[br * WSLICE + (cg * 4 + c) * K_ + k];
#pragma unroll
            for (int br = 0; br < 2; br++)
#pragma unroll
                for (int c = 0; c < 4; c++)
#pragma unroll
                    for (int p = 0; p < 4; p++) {
                        unsigned long long xp = (k & 1) ? xo[(k >> 1) + p]
                                                        : xe[(k >> 1) + p];
                        fma2(acc[br][c][p], xp, wv[br][c]);
                    }
        }
        __syncthreads();
    }

    // epilogue: store y, accumulate per-channel sum / sumsq
    const int tbase = t0 + tg * 8;
#pragma unroll
    for (int br = 0; br < 2; br++) {
#pragma unroll
        for (int c = 0; c < 4; c++) {
            const int co = cg * 4 + c;
            float v[8];
#pragma unroll
            for (int p = 0; p < 4; p++) {
                float2 f = upk(acc[br][c][p]);
                v[2 * p] = f.x; v[2 * p + 1] = f.y;
            }
            float ls = 0.f, lss = 0.f;
            float* yp = g_y + (size_t)((br * B_ + b) * C_ + co) * TP_ + tbase;
#pragma unroll
            for (int j = 0; j < 8; j++) {
                if (tbase + j < TC_) {
                    yp[j] = v[j];
                    ls  += v[j];
                    lss += v[j] * v[j];
                }
            }
#pragma unroll
            for (int o = 8; o; o >>= 1) {
                ls  += __shfl_xor_sync(0xffffffffu, ls, o);
                lss += __shfl_xor_sync(0xffffffffu, lss, o);
            }
            if (tg == 0) {
                atomicAdd(&g_sum[br * C_ + co], ls);
                atomicAdd(&g_sumsq[br * C_ + co], lss);
            }
        }
    }
}

// ---------------- kernel 3: finalize BN affine ------------------------------
__global__ void finalize_kernel(const float* __restrict__ g1, const float* __restrict__ b1,
                                const float* __restrict__ g2, const float* __restrict__ b2) {
    int i = threadIdx.x;
    if (i < 2 * C_) {
        int br = i >> 6, c = i & 63;
        const float Nf = (float)(B_ * TC_);
        float mean = g_sum[i] / Nf;
        float var  = g_sumsq[i] / Nf - mean * mean;
        float gamma = br ? g2[c] : g1[c];
        float beta  = br ? b2[c] : b1[c];
        float a = gamma * rsqrtf(var + 1e-5f);
        g_scale[i] = a;
        g_shift[i] = beta - mean * a;
    }
}

// ---------------- kernel 4: SPP pooling (affine + LeakyReLU fused) ----------
__global__ __launch_bounds__(256) void pool_kernel(const int* __restrict__ orig_len) {
    const int co = blockIdx.x, b = blockIdx.y, br = blockIdx.z;
    const int L    = orig_len[b] - (K_ - 1);
    const int str  = L >> 1;
    const int kern = L - str;            // ceil(L/2)
    const float a  = g_scale[br * C_ + co];
    const float c0 = g_shift[br * C_ + co];
    const float* yp = g_y + (size_t)((br * B_ + b) * C_ + co) * TP_;
    const int tid = threadIdx.x;
    const float NINF = __int_as_float(0xff800000);

    float r0, r1, r2;
    if (br == 0) {
        float m = NINF, m0 = NINF, m1 = NINF;
        for (int t = tid; t < L; t += 256) {
            float v = fmaf(yp[t], a, c0);
            v = (v > 0.f) ? v : NEG * v;
            m = fmaxf(m, v);
            if (t < kern)  m0 = fmaxf(m0, v);
            if (t >= str)  m1 = fmaxf(m1, v);
        }
        r0 = m; r1 = m0; r2 = m1;
    } else {
        float s = 0.f, s0 = 0.f, s1 = 0.f;
        for (int t = tid; t < L; t += 256) {
            float v = fmaf(yp[t], a, c0);
            v = (v > 0.f) ? v : NEG * v;
            s += v;
            if (t < kern)  s0 += v;
            if (t >= str)  s1 += v;
        }
        r0 = s; r1 = s0; r2 = s1;
    }

    __shared__ float sred[3][8];
    const int lane = tid & 31, wrp = tid >> 5;
    if (br == 0) {
#pragma unroll
        for (int o = 16; o; o >>= 1) {
            r0 = fmaxf(r0, __shfl_xor_sync(0xffffffffu, r0, o));
            r1 = fmaxf(r1, __shfl_xor_sync(0xffffffffu, r1, o));
            r2 = fmaxf(r2, __shfl_xor_sync(0xffffffffu, r2, o));
        }
    } else {
#pragma unroll
        for (int o = 16; o; o >>= 1) {
            r0 += __shfl_xor_sync(0xffffffffu, r0, o);
            r1 += __shfl_xor_sync(0xffffffffu, r1, o);
            r2 += __shfl_xor_sync(0xffffffffu, r2, o);
        }
    }
    if (lane == 0) { sred[0][wrp] = r0; sred[1][wrp] = r1; sred[2][wrp] = r2; }
    __syncthreads();
    if (tid == 0) {
        float a0 = sred[0][0], a1 = sred[1][0], a2 = sred[2][0];
        for (int w = 1; w < 8; w++) {
            if (br == 0) {
                a0 = fmaxf(a0, sred[0][w]);
                a1 = fmaxf(a1, sred[1][w]);
                a2 = fmaxf(a2, sred[2][w]);
            } else {
                a0 += sred[0][w]; a1 += sred[1][w]; a2 += sred[2][w];
            }
        }
        float* f = g_feat + b * 384;
        if (br == 0) {
            f[co] = a0;
            f[64 + 2 * co]     = a1;
            f[64 + 2 * co + 1] = a2;
        } else {
            f[192 + co] = a0 / (float)L;
            f[256 + 2 * co]     = a1 / (float)kern;
            f[256 + 2 * co + 1] = a2 / (float)kern;
        }
    }
}

// ---------------- kernel 5: FC head ----------------------------------------
__global__ void fc_kernel(const float* __restrict__ fcw, const float* __restrict__ fcb,
                          float* __restrict__ out) {
    int i = threadIdx.x;
    if (i < B_ * 2) {
        int b = i >> 1, t = i & 1;
        float acc = fcb[t];
        const float* f = g_feat + b * 384;
        const float* w = fcw + t * 384;
#pragma unroll 8
        for (int j = 0; j < 384; j++) acc += f[j] * w[j];
        out[i] = acc;   // i == b*2 + t, row-major (B, 2)
    }
}

// ---------------- launch ----------------------------------------------------
extern "C" void kernel_launch(void* const* d_in, const int* in_sizes, int n_in,
                              void* d_out, int out_size) {
    const float* x        = (const float*)d_in[0];
    const int*   orig_len = (const int*)  d_in[1];
    const float* w1       = (const float*)d_in[2];
    const float* g1       = (const float*)d_in[3];
    const float* b1       = (const float*)d_in[4];
    const float* w2       = (const float*)d_in[5];
    const float* g2       = (const float*)d_in[6];
    const float* b2       = (const float*)d_in[7];
    const float* fcw      = (const float*)d_in[8];
    const float* fcb      = (const float*)d_in[9];
    float* out = (float*)d_out;

    cudaFuncSetAttribute(conv_kernel, cudaFuncAttributeMaxDynamicSharedMemorySize,
                         SMEM_BYTES);

    zero_kernel<<<1, 128>>>();
    wpack_kernel<<<(2 * C_ * C_ * K_ + 255) / 256, 256>>>(w1, w2);
    conv_kernel<<<dim3(NTILES, B_), 256, SMEM_BYTES>>>(x);
    finalize_kernel<<<1, 128>>>(g1, b1, g2, b2);
    pool_kernel<<<dim3(C_, B_, 2), 256>>>(orig_len);
    fc_kernel<<<1, 64>>>(fcw, fcb, out);
}

// round 3
// speedup vs baseline: 1.4077x; 1.4077x over previous
#include <cuda_runtime.h>
#include <cstdint>
#include <cstddef>

#define B_ 32
#define C_ 64
#define T_ 16384
#define K_ 21
#define KP 22           // K padded to even so (co*KP+k)*8B is 16B-aligned for even k
#define TC_ 16364       // T - (K-1)
#define TP_ 16384       // padded time stride for scratch
#define TILE_T 128
#define NTILES 128      // ceil(TC_/TILE_T)
#define NEG 0.01f
#define WSL 1408        // C_ * KP float2 per (br, ci)
#define XW 152          // staged x row width (floats), 16B-aligned rows
#define SMEM_BYTES (2*64*XW*4 + 2*2*WSL*8)   // xs+xsh (77824) + dbl-buf weights (45056)

// ---------------- device scratch (static: no allocations allowed) -----------
__device__ float  g_y[(size_t)2 * B_ * C_ * TP_];          // conv out [br][b][co][t]
__device__ __align__(16) float2 g_wp[2 * C_ * WSL];        // packed (w,w) [br][ci][co][kp]
__device__ float  g_sum[2 * C_], g_sumsq[2 * C_];
__device__ float  g_scale[2 * C_], g_shift[2 * C_];
__device__ float  g_feat[B_ * 384];

// ---------------- f32x2 helpers ---------------------------------------------
__device__ __forceinline__ void fma2(unsigned long long& a, unsigned long long x,
                                     unsigned long long w) {
    asm("fma.rn.f32x2 %0, %1, %2, %0;" : "+l"(a) : "l"(x), "l"(w));
}
__device__ __forceinline__ float2 upk(unsigned long long v) {
    float2 f;
    asm("mov.b64 {%0, %1}, %2;" : "=f"(f.x), "=f"(f.y) : "l"(v));
    return f;
}

// ---------------- kernel 0: zero per-channel stats --------------------------
__global__ void zero_kernel() {
    int i = threadIdx.x;
    if (i < 2 * C_) { g_sum[i] = 0.f; g_sumsq[i] = 0.f; }
}

// ---------------- kernel 1: pre-pack weights as (w,w) float2, K padded ------
__global__ void wpack_kernel(const float* __restrict__ w1,
                             const float* __restrict__ w2) {
    int idx = blockIdx.x * blockDim.x + threadIdx.x;
    if (idx >= 2 * C_ * WSL) return;
    int br = idx / (C_ * WSL);
    int r  = idx - br * (C_ * WSL);
    int ci = r / WSL;
    int r2 = r - ci * WSL;
    int co = r2 / KP;
    int k  = r2 - co * KP;
    float v = 0.f;
    if (k < K_) {
        const float* w = br ? w2 : w1;
        v = w[(co * C_ + ci) * K_ + k];
    }
    g_wp[idx] = make_float2(v, v);
}

// ---------------- pad kernel (aligns ncu -s slot onto conv) -----------------
__global__ void pad_kernel() {}

// ---------------- cp.async weight staging -----------------------------------
__device__ __forceinline__ void stage_w(int ci, int buf, uint32_t ws_base, int tid) {
    // 2 branches x WSL float2 = 1408 chunks of 16 bytes
    for (int c = tid; c < 1408; c += 256) {
        int br  = (c >= 704);
        int off = (c - br * 704) * 2;                    // float2 offset
        const float2* src = g_wp + (size_t)(br * C_ + ci) * WSL + off;
        uint32_t dst = ws_base + (uint32_t)(buf * (2 * WSL * 8) + (br * WSL + off) * 8);
        asm volatile("cp.async.cg.shared.global [%0], [%1], 16;"
                     :: "r"(dst), "l"(src));
    }
    asm volatile("cp.async.commit_group;" ::: "memory");
}

// ---------------- kernel 2: fused conv (both branches) + stats --------------
// 256 threads: tg = tid&15 (8 t each), cg = tid>>4 (4 co each)
__global__ __launch_bounds__(256, 1) void conv_kernel(const float* __restrict__ x) {
    extern __shared__ float sh[];
    float*  xs  = sh;                        // [64][XW]
    float*  xsh = sh + 64 * XW;              // [64][XW], shifted by 1 element
    float2* ws  = (float2*)(sh + 2 * 64 * XW); // [2 buf][2*WSL]

    const int b   = blockIdx.y;
    const int t0  = blockIdx.x * TILE_T;
    const int tid = threadIdx.x;

    // stage x tile + shifted copy (zero-pad tail)
    for (int idx = tid; idx < 64 * XW; idx += 256) {
        int ci = idx / XW, j = idx - ci * XW;
        int gt = t0 + j;
        float v = (gt < T_) ? x[((size_t)b * C_ + ci) * T_ + gt] : 0.f;
        xs[idx] = v;
        if (j > 0)      xsh[idx - 1] = v;
        if (j == XW - 1) xsh[idx] = 0.f;
    }

    uint32_t ws_u32 = (uint32_t)__cvta_generic_to_shared(ws);
    stage_w(0, 0, ws_u32, tid);

    const int tg = tid & 15;
    const int cg = tid >> 4;

    unsigned long long acc[2][4][4];
#pragma unroll
    for (int br = 0; br < 2; br++)
#pragma unroll
        for (int c = 0; c < 4; c++)
#pragma unroll
            for (int p = 0; p < 4; p++) acc[br][c][p] = 0ULL;

    for (int ci = 0; ci < C_; ++ci) {
        asm volatile("cp.async.wait_group 0;" ::: "memory");
        __syncthreads();
        if (ci + 1 < C_) stage_w(ci + 1, (ci + 1) & 1, ws_u32, tid);

        const float2* wrow = ws + (ci & 1) * (2 * WSL);

        // x window: even pairs from xs, odd pairs from xsh (all aligned LDS.128)
        unsigned long long xe[14], xo[14];
        const ulonglong2* pe = (const ulonglong2*)(xs  + ci * XW + tg * 8);
        const ulonglong2* po = (const ulonglong2*)(xsh + ci * XW + tg * 8);
#pragma unroll
        for (int m = 0; m < 7; m++) {
            ulonglong2 q = pe[m]; xe[2 * m] = q.x; xe[2 * m + 1] = q.y;
            ulonglong2 r = po[m]; xo[2 * m] = r.x; xo[2 * m + 1] = r.y;
        }

#pragma unroll
        for (int kk = 0; kk < 20; kk += 2) {
            unsigned long long wlo[2][4], whi[2][4];
#pragma unroll
            for (int br = 0; br < 2; br++)
#pragma unroll
                for (int c = 0; c < 4; c++) {
                    ulonglong2 wq = *(const ulonglong2*)
                        &wrow[br * WSL + (cg * 4 + c) * KP + kk];
                    wlo[br][c] = wq.x; whi[br][c] = wq.y;
                }
#pragma unroll
            for (int br = 0; br < 2; br++)
#pragma unroll
                for (int c = 0; c < 4; c++)
#pragma unroll
                    for (int p = 0; p < 4; p++) {
                        fma2(acc[br][c][p], xe[(kk >> 1) + p], wlo[br][c]);
                        fma2(acc[br][c][p], xo[(kk >> 1) + p], whi[br][c]);
                    }
        }
        // k = 20 tail
#pragma unroll
        for (int br = 0; br < 2; br++)
#pragma unroll
            for (int c = 0; c < 4; c++) {
                unsigned long long w20 = *(const unsigned long long*)
                    &wrow[br * WSL + (cg * 4 + c) * KP + 20];
#pragma unroll
                for (int p = 0; p < 4; p++)
                    fma2(acc[br][c][p], xe[10 + p], w20);
            }
    }

    // epilogue: store y, accumulate per-channel sum / sumsq
    const int tbase = t0 + tg * 8;
#pragma unroll
    for (int br = 0; br < 2; br++) {
#pragma unroll
        for (int c = 0; c < 4; c++) {
            const int co = cg * 4 + c;
            float v[8];
#pragma unroll
            for (int p = 0; p < 4; p++) {
                float2 f = upk(acc[br][c][p]);
                v[2 * p] = f.x; v[2 * p + 1] = f.y;
            }
            float ls = 0.f, lss = 0.f;
            float* yp = g_y + (size_t)((br * B_ + b) * C_ + co) * TP_ + tbase;
#pragma unroll
            for (int j = 0; j < 8; j++) {
                if (tbase + j < TC_) {
                    yp[j] = v[j];
                    ls  += v[j];
                    lss += v[j] * v[j];
                }
            }
#pragma unroll
            for (int o = 8; o; o >>= 1) {
                ls  += __shfl_xor_sync(0xffffffffu, ls, o);
                lss += __shfl_xor_sync(0xffffffffu, lss, o);
            }
            if (tg == 0) {
                atomicAdd(&g_sum[br * C_ + co], ls);
                atomicAdd(&g_sumsq[br * C_ + co], lss);
            }
        }
    }
}

// ---------------- kernel 3: finalize BN affine ------------------------------
__global__ void finalize_kernel(const float* __restrict__ g1, const float* __restrict__ b1,
                                const float* __restrict__ g2, const float* __restrict__ b2) {
    int i = threadIdx.x;
    if (i < 2 * C_) {
        int br = i >> 6, c = i & 63;
        const float Nf = (float)(B_ * TC_);
        float mean = g_sum[i] / Nf;
        float var  = g_sumsq[i] / Nf - mean * mean;
        float gamma = br ? g2[c] : g1[c];
        float beta  = br ? b2[c] : b1[c];
        float a = gamma * rsqrtf(var + 1e-5f);
        g_scale[i] = a;
        g_shift[i] = beta - mean * a;
    }
}

// ---------------- kernel 4: SPP pooling (affine + LeakyReLU fused) ----------
__global__ __launch_bounds__(256) void pool_kernel(const int* __restrict__ orig_len) {
    const int co = blockIdx.x, b = blockIdx.y, br = blockIdx.z;
    const int L    = orig_len[b] - (K_ - 1);
    const int str  = L >> 1;
    const int kern = L - str;            // ceil(L/2)
    const float a  = g_scale[br * C_ + co];
    const float c0 = g_shift[br * C_ + co];
    const float* yp = g_y + (size_t)((br * B_ + b) * C_ + co) * TP_;
    const int tid = threadIdx.x;
    const float NINF = __int_as_float(0xff800000);

    float r0, r1, r2;
    if (br == 0) {
        float m = NINF, m0 = NINF, m1 = NINF;
        for (int t = tid; t < L; t += 256) {
            float v = fmaf(yp[t], a, c0);
            v = (v > 0.f) ? v : NEG * v;
            m = fmaxf(m, v);
            if (t < kern)  m0 = fmaxf(m0, v);
            if (t >= str)  m1 = fmaxf(m1, v);
        }
        r0 = m; r1 = m0; r2 = m1;
    } else {
        float s = 0.f, s0 = 0.f, s1 = 0.f;
        for (int t = tid; t < L; t += 256) {
            float v = fmaf(yp[t], a, c0);
            v = (v > 0.f) ? v : NEG * v;
            s += v;
            if (t < kern)  s0 += v;
            if (t >= str)  s1 += v;
        }
        r0 = s; r1 = s0; r2 = s1;
    }

    __shared__ float sred[3][8];
    const int lane = tid & 31, wrp = tid >> 5;
    if (br == 0) {
#pragma unroll
        for (int o = 16; o; o >>= 1) {
            r0 = fmaxf(r0, __shfl_xor_sync(0xffffffffu, r0, o));
            r1 = fmaxf(r1, __shfl_xor_sync(0xffffffffu, r1, o));
            r2 = fmaxf(r2, __shfl_xor_sync(0xffffffffu, r2, o));
        }
    } else {
#pragma unroll
        for (int o = 16; o; o >>= 1) {
            r0 += __shfl_xor_sync(0xffffffffu, r0, o);
            r1 += __shfl_xor_sync(0xffffffffu, r1, o);
            r2 += __shfl_xor_sync(0xffffffffu, r2, o);
        }
    }
    if (lane == 0) { sred[0][wrp] = r0; sred[1][wrp] = r1; sred[2][wrp] = r2; }
    __syncthreads();
    if (tid == 0) {
        float a0 = sred[0][0], a1 = sred[1][0], a2 = sred[2][0];
        for (int w = 1; w < 8; w++) {
            if (br == 0) {
                a0 = fmaxf(a0, sred[0][w]);
                a1 = fmaxf(a1, sred[1][w]);
                a2 = fmaxf(a2, sred[2][w]);
            } else {
                a0 += sred[0][w]; a1 += sred[1][w]; a2 += sred[2][w];
            }
        }
        float* f = g_feat + b * 384;
        if (br == 0) {
            f[co] = a0;
            f[64 + 2 * co]     = a1;
            f[64 + 2 * co + 1] = a2;
        } else {
            f[192 + co] = a0 / (float)L;
            f[256 + 2 * co]     = a1 / (float)kern;
            f[256 + 2 * co + 1] = a2 / (float)kern;
        }
    }
}

// ---------------- kernel 5: FC head ----------------------------------------
__global__ void fc_kernel(const float* __restrict__ fcw, const float* __restrict__ fcb,
                          float* __restrict__ out) {
    int i = threadIdx.x;
    if (i < B_ * 2) {
        int b = i >> 1, t = i & 1;
        float acc = fcb[t];
        const float* f = g_feat + b * 384;
        const float* w = fcw + t * 384;
#pragma unroll 8
        for (int j = 0; j < 384; j++) acc += f[j] * w[j];
        out[i] = acc;
    }
}

// ---------------- launch ----------------------------------------------------
extern "C" void kernel_launch(void* const* d_in, const int* in_sizes, int n_in,
                              void* d_out, int out_size) {
    const float* x        = (const float*)d_in[0];
    const int*   orig_len = (const int*)  d_in[1];
    const float* w1       = (const float*)d_in[2];
    const float* g1       = (const float*)d_in[3];
    const float* b1       = (const float*)d_in[4];
    const float* w2       = (const float*)d_in[5];
    const float* g2       = (const float*)d_in[6];
    const float* b2       = (const float*)d_in[7];
    const float* fcw      = (const float*)d_in[8];
    const float* fcb      = (const float*)d_in[9];
    float* out = (float*)d_out;

    cudaFuncSetAttribute(conv_kernel, cudaFuncAttributeMaxDynamicSharedMemorySize,
                         SMEM_BYTES);

    zero_kernel<<<1, 128>>>();
    wpack_kernel<<<(2 * C_ * WSL + 255) / 256, 256>>>(w1, w2);
    pad_kernel<<<1, 32>>>();   // shifts the ncu -s window so conv is profiled
    conv_kernel<<<dim3(NTILES, B_), 256, SMEM_BYTES>>>(x);
    finalize_kernel<<<1, 128>>>(g1, b1, g2, b2);
    pool_kernel<<<dim3(C_, B_, 2), 256>>>(orig_len);
    fc_kernel<<<1, 64>>>(fcw, fcb, out);
}